// round 12
// baseline (speedup 1.0000x reference)
#include <cuda_runtime.h>
#include <cuda_bf16.h>
#include <cstdint>

#define NB 8
#define NT 1024
#define ND 512
#define NH 8
#define NDH 64
#define NSPOS 2047
#define ATT_SCALE 0.125f

typedef unsigned long long ull;

// ---------------- scratch (device globals; no allocs allowed) ----------------
__device__ float g_q[NB*NH*NT*NDH];
__device__ float g_k[NB*NH*NT*NDH];
__device__ float g_v[NB*NH*NT*NDH];
__device__ float g_p[NH*NSPOS*NDH];
__device__ float g_ao[NB*NT*ND];
__device__ float g_uk[NB*NH*NT];
__device__ float g_vp[NH*NSPOS];
__device__ __nv_bfloat16 g_xh[NB*NT*ND],  g_xl[NB*NT*ND];
__device__ __nv_bfloat16 g_peh[2048*ND],  g_pel[2048*ND];
__device__ __nv_bfloat16 g_wth[5*ND*ND],  g_wtl[5*ND*ND];
__device__ __nv_bfloat16 g_aoh[NB*NT*ND], g_aol[NB*NT*ND];

// ---------------- scalar f32x2 helpers (attention) ----------------
__device__ __forceinline__ void ffma2(ull &d, ull a, ull b) {
    asm("fma.rn.f32x2 %0, %1, %2, %0;" : "+l"(d) : "l"(a), "l"(b));
}
__device__ __forceinline__ void fmul2(ull &d, ull a) {
    asm("mul.rn.f32x2 %0, %0, %1;" : "+l"(d) : "l"(a));
}
__device__ __forceinline__ ull fdup(float x) {
    ull r; asm("mov.b64 %0, {%1, %1};" : "=l"(r) : "f"(x)); return r;
}
__device__ __forceinline__ float2 unpk(ull v) {
    float2 f; asm("mov.b64 {%0, %1}, %2;" : "=f"(f.x), "=f"(f.y) : "l"(v)); return f;
}

// ---------------- mma.sync / ldmatrix / cp.async helpers ----------------
__device__ __forceinline__ uint32_t smem_u32(const void* p) {
    uint32_t a;
    asm("{ .reg .u64 t; cvta.to.shared.u64 t, %1; cvt.u32.u64 %0, t; }" : "=r"(a) : "l"(p));
    return a;
}
#define LDSM4(r, addr) \
    asm volatile("ldmatrix.sync.aligned.m8n8.x4.shared.b16 {%0,%1,%2,%3}, [%4];" \
        : "=r"((r)[0]), "=r"((r)[1]), "=r"((r)[2]), "=r"((r)[3]) : "r"(addr))
#define MMA16816(c, a, b0, b1) \
    asm volatile("mma.sync.aligned.m16n8k16.row.col.f32.bf16.bf16.f32 " \
        "{%0,%1,%2,%3}, {%4,%5,%6,%7}, {%8,%9}, {%0,%1,%2,%3};" \
        : "+f"((c)[0]), "+f"((c)[1]), "+f"((c)[2]), "+f"((c)[3]) \
        : "r"((a)[0]), "r"((a)[1]), "r"((a)[2]), "r"((a)[3]), "r"(b0), "r"(b1))
__device__ __forceinline__ void cpa16(uint32_t dst, const void* src, int sz) {
    asm volatile("cp.async.cg.shared.global [%0], [%1], 16, %2;"
                 :: "r"(dst), "l"(src), "r"(sz) : "memory");
}
__device__ __forceinline__ void cpa_commit() {
    asm volatile("cp.async.commit_group;" ::: "memory");
}
__device__ __forceinline__ void cpa_wait0() {
    asm volatile("cp.async.wait_group 0;" ::: "memory");
}

// ---------------- split-precision convert kernels ----------------
__global__ __launch_bounds__(256)
void split_k(const float* __restrict__ s, __nv_bfloat16* __restrict__ h,
             __nv_bfloat16* __restrict__ l, int n4)
{
    int i = blockIdx.x * 256 + threadIdx.x;
    if (i >= n4) return;
    float4 v = ((const float4*)s)[i];
    __nv_bfloat16 h0 = __float2bfloat16(v.x), h1 = __float2bfloat16(v.y);
    __nv_bfloat16 h2 = __float2bfloat16(v.z), h3 = __float2bfloat16(v.w);
    __nv_bfloat16 l0 = __float2bfloat16(v.x - __bfloat162float(h0));
    __nv_bfloat16 l1 = __float2bfloat16(v.y - __bfloat162float(h1));
    __nv_bfloat16 l2 = __float2bfloat16(v.z - __bfloat162float(h2));
    __nv_bfloat16 l3 = __float2bfloat16(v.w - __bfloat162float(h3));
    ((__nv_bfloat162*)h)[i*2+0] = __nv_bfloat162(h0, h1);
    ((__nv_bfloat162*)h)[i*2+1] = __nv_bfloat162(h2, h3);
    ((__nv_bfloat162*)l)[i*2+0] = __nv_bfloat162(l0, l1);
    ((__nv_bfloat162*)l)[i*2+1] = __nv_bfloat162(l2, l3);
}

// Transpose + split the 5 weight matrices: wt[z][n][k] = W_z[k][n]
__global__ __launch_bounds__(256)
void wsplit_k(const float* __restrict__ W0, const float* __restrict__ W1,
              const float* __restrict__ W2, const float* __restrict__ W3,
              const float* __restrict__ W4,
              __nv_bfloat16* __restrict__ th, __nv_bfloat16* __restrict__ tl)
{
    const float* W;
    switch (blockIdx.z) {
        case 0: W = W0; break;
        case 1: W = W1; break;
        case 2: W = W2; break;
        case 3: W = W3; break;
        default: W = W4; break;
    }
    __shared__ float t[32][33];
    int tx = threadIdx.x & 31, ty = threadIdx.x >> 5;
    int n0 = blockIdx.x * 32, k0 = blockIdx.y * 32;
#pragma unroll
    for (int ph = 0; ph < 4; ph++)
        t[ty + ph * 8][tx] = W[(size_t)(k0 + ty + ph * 8) * ND + n0 + tx];
    __syncthreads();
    size_t base = (size_t)blockIdx.z * ND * ND;
#pragma unroll
    for (int ph = 0; ph < 4; ph++) {
        int n = n0 + ty + ph * 8, k = k0 + tx;
        float v = t[tx][ty + ph * 8];
        __nv_bfloat16 hh = __float2bfloat16(v);
        __nv_bfloat16 ll = __float2bfloat16(v - __bfloat162float(hh));
        th[base + (size_t)n * ND + k] = hh;
        tl[base + (size_t)n * ND + k] = ll;
    }
}

// ---------------------------------------------------------------------------
// mma.sync split-bf16 GEMM (unchanged from R11).
// ---------------------------------------------------------------------------
#define MT_AH 0
#define MT_AL 10240
#define MT_BH 20480
#define MT_BL 30720
#define MT_BUF 40960
#define MT_SMEM 81920

template<int MODE>
__device__ __forceinline__
void mmagemm_body(const __nv_bfloat16* __restrict__ Ah, const __nv_bfloat16* __restrict__ Al,
                  const __nv_bfloat16* __restrict__ Bh, const __nv_bfloat16* __restrict__ Bl,
                  const float* __restrict__ bias, float* __restrict__ C,
                  int M, int row0, int col0, char* smraw)
{
    const int tid  = threadIdx.x;
    const int lane = tid & 31;
    const int wid  = tid >> 5;
    const int warp_m = wid >> 2;
    const int warp_n = wid & 3;
    const uint32_t smb = smem_u32(smraw);

    const int ldrow = tid >> 1;
    const int ldc8  = (tid & 1) * 16;
    const bool okA  = (row0 + ldrow) < M;
    const size_t agoff = (size_t)(row0 + ldrow) * ND;
    const size_t bgoff = (size_t)(col0 + ldrow) * ND;
    const uint32_t srow = (uint32_t)ldrow * 40;
    const int szA = okA ? 16 : 0;

    float acc[4][4][4];
#pragma unroll
    for (int mi = 0; mi < 4; mi++)
#pragma unroll
        for (int ni = 0; ni < 4; ni++)
#pragma unroll
            for (int e = 0; e < 4; e++) acc[mi][ni][e] = 0.f;

    const int a_row = warp_m * 64 + (lane & 7) + ((lane >> 3) & 1) * 8;
    const int b_row = warp_n * 32 + (lane & 7) + ((lane >> 3) & 1) * 8;
    const int lm_k  = (lane >> 4) * 8;

    auto load_tile = [&](int k0, int buf) {
        uint32_t sb = smb + buf * MT_BUF;
#pragma unroll
        for (int c = 0; c < 2; c++) {
            int col = ldc8 + c * 8;
            uint32_t so = (srow + col) * 2;
            cpa16(sb + MT_AH + so, Ah + agoff + k0 + col, szA);
            cpa16(sb + MT_AL + so, Al + agoff + k0 + col, szA);
            cpa16(sb + MT_BH + so, Bh + bgoff + k0 + col, 16);
            cpa16(sb + MT_BL + so, Bl + bgoff + k0 + col, 16);
        }
    };

    load_tile(0, 0);
    cpa_commit();

    int buf = 0;
    for (int it = 0; it < 16; it++) {
        cpa_wait0();
        __syncthreads();
        if (it < 15) {
            load_tile((it + 1) * 32, buf ^ 1);
            cpa_commit();
        }
        const uint32_t sb = smb + buf * MT_BUF;
#pragma unroll
        for (int ks = 0; ks < 2; ks++) {
            const int kofs = ks * 16 + lm_k;
            uint32_t bh[2][4], bl[2][4];
#pragma unroll
            for (int p = 0; p < 2; p++) {
                uint32_t off = (uint32_t)((b_row + p * 16) * 40 + kofs) * 2;
                LDSM4(bh[p], sb + MT_BH + off);
                LDSM4(bl[p], sb + MT_BL + off);
            }
#pragma unroll
            for (int mi = 0; mi < 4; mi++) {
                uint32_t ah[4], al[4];
                uint32_t off = (uint32_t)((a_row + mi * 16) * 40 + kofs) * 2;
                LDSM4(ah, sb + MT_AH + off);
                LDSM4(al, sb + MT_AL + off);
#pragma unroll
                for (int ni = 0; ni < 4; ni++) {
                    const int p = ni >> 1, hi = ni & 1;
                    MMA16816(acc[mi][ni], ah, bh[p][hi], bh[p][hi + 2]);
                    MMA16816(acc[mi][ni], ah, bl[p][hi], bl[p][hi + 2]);
                    MMA16816(acc[mi][ni], al, bh[p][hi], bh[p][hi + 2]);
                }
            }
        }
        buf ^= 1;
    }

#pragma unroll
    for (int mi = 0; mi < 4; mi++) {
        const int r0 = row0 + warp_m * 64 + mi * 16 + (lane >> 2);
#pragma unroll
        for (int ni = 0; ni < 4; ni++) {
            const int col = col0 + warp_n * 32 + ni * 8 + (lane & 3) * 2;
            const float b0 = bias ? bias[col] : 0.f;
            const float b1 = bias ? bias[col + 1] : 0.f;
#pragma unroll
            for (int half = 0; half < 2; half++) {
                const int m = r0 + half * 8;
                if (m >= M) continue;
                float2 o;
                o.x = acc[mi][ni][half * 2 + 0] + b0;
                o.y = acc[mi][ni][half * 2 + 1] + b1;
                if (MODE == 0) {
                    *(float2*)(C + (size_t)m * ND + col) = o;
                } else if (MODE == 1) {
                    int b = m >> 10, t = m & 1023;
                    int h = col >> 6, d = col & 63;
                    *(float2*)(C + ((size_t)((b << 3) + h) * NT + t) * NDH + d) = o;
                } else {
                    int h = col >> 6, d = col & 63;
                    *(float2*)(C + ((size_t)h * NSPOS + m) * NDH + d) = o;
                }
            }
        }
    }
}

template<int MODE>
__global__ __launch_bounds__(256, 2)
void mmagemm_k(const __nv_bfloat16* __restrict__ Ah, const __nv_bfloat16* __restrict__ Al,
               const __nv_bfloat16* __restrict__ Bh, const __nv_bfloat16* __restrict__ Bl,
               const float* __restrict__ bias, float* __restrict__ C, int M)
{
    extern __shared__ char smraw[];
    mmagemm_body<MODE>(Ah, Al, Bh, Bl, bias, C, M,
                       blockIdx.x << 7, blockIdx.y << 7, smraw);
}

__global__ __launch_bounds__(256, 2)
void mmagemm_fused_k(const __nv_bfloat16* __restrict__ xh, const __nv_bfloat16* __restrict__ xl,
                     const __nv_bfloat16* __restrict__ peh, const __nv_bfloat16* __restrict__ pel,
                     const __nv_bfloat16* __restrict__ wth, const __nv_bfloat16* __restrict__ wtl,
                     const float* __restrict__ bq, const float* __restrict__ bk,
                     const float* __restrict__ bv,
                     float* __restrict__ Cq, float* __restrict__ Ck,
                     float* __restrict__ Cv, float* __restrict__ Cp)
{
    extern __shared__ char smraw[];
    const int z = blockIdx.z;
    const size_t WSZ = (size_t)ND * ND;
    if (z == 3) {
        if (blockIdx.x >= 16) return;
        mmagemm_body<2>(peh, pel, wth + 3 * WSZ, wtl + 3 * WSZ, nullptr, Cp, NSPOS,
                        blockIdx.x << 7, blockIdx.y << 7, smraw);
    } else {
        const float* bias = (z == 0) ? bq : (z == 1) ? bk : bv;
        float* C = (z == 0) ? Cq : (z == 1) ? Ck : Cv;
        mmagemm_body<1>(xh, xl, wth + z * WSZ, wtl + z * WSZ, bias, C, NB * NT,
                        blockIdx.x << 7, blockIdx.y << 7, smraw);
    }
}

// ---------------------------------------------------------------------------
// Precompute uk / vp rank-1 terms.
// ---------------------------------------------------------------------------
#define NUKROWS (NB*NH*NT)
#define NVPROWS (NH*NSPOS)
__global__ __launch_bounds__(256)
void biasdot_k(const float* __restrict__ k, const float* __restrict__ p,
               const float* __restrict__ pbu, const float* __restrict__ pbv,
               float* __restrict__ uk, float* __restrict__ vp)
{
    int w = (blockIdx.x * 256 + threadIdx.x) >> 5;
    int lane = threadIdx.x & 31;
    if (w < NUKROWS) {
        int h = (w >> 10) & 7;
        float2 a = *(const float2*)(k + (size_t)w * NDH + lane * 2);
        float2 u = *(const float2*)(pbu + h * NDH + lane * 2);
        float s = a.x * u.x + a.y * u.y;
#pragma unroll
        for (int off = 16; off >= 1; off >>= 1)
            s += __shfl_xor_sync(0xffffffffu, s, off);
        if (lane == 0) uk[w] = s;
    } else if (w < NUKROWS + NVPROWS) {
        int r = w - NUKROWS;
        float2 a = *(const float2*)(p + (size_t)r * NDH + lane * 2);
        int h = r / NSPOS;
        float2 u = *(const float2*)(pbv + h * NDH + lane * 2);
        float s = a.x * u.x + a.y * u.y;
#pragma unroll
        for (int off = 16; off >= 1; off >>= 1)
            s += __shfl_xor_sync(0xffffffffu, s, off);
        if (lane == 0) vp[r] = s;
    }
}

// ---------------------------------------------------------------------------
// Flash attention: 128q x 64k tiles, 512 threads (16 warps), 4x4 frags.
// tx = tid>>4 in [0,32): rows r = tx+32i.  ty = tid&15: cols c = ty+16j.
// band row = (ty-tx+31) + 16*(j-2i+6); pv index m = j-2i+6 in [0,10).
// ---------------------------------------------------------------------------
#define SQ_OFF 0               // [128][64] swizzled
#define SK_OFF 8192            // [64][64] swizzled
#define SP_OFF 12288           // [191][64] swizzled
#define SV_OFF 24512           // [64][68] linear
#define SPR_OFF 28864          // [128][66]
#define SUK_OFF 37312          // [64]
#define SVP_OFF 37376          // [191]
#define SM_FLOATS 37600

__global__ __launch_bounds__(512)
void attn_k(const float* __restrict__ q, const float* __restrict__ k,
            const float* __restrict__ v, const float* __restrict__ p,
            const float* __restrict__ uk, const float* __restrict__ vp,
            float* __restrict__ out)
{
    extern __shared__ float sm[];
    float* sq  = sm + SQ_OFF;
    float* sk_ = sm + SK_OFF;
    float* sp_ = sm + SP_OFF;
    float* sv_ = sm + SV_OFF;
    float* sPs = sm + SPR_OFF;
    float* suk = sm + SUK_OFF;
    float* svp = sm + SVP_OFF;

    const int tid = threadIdx.x;
    const int tx = tid >> 4;     // 0..31 (row group)
    const int ty = tid & 15;     // 0..15 (col group)
    const int bx = blockIdx.x;
    const int t0 = (bx & 7) << 7;
    const int bh = bx >> 3;
    const int h  = bh & 7;
    const int b  = bh >> 3;

    const float* qb = q + ((size_t)bh * NT + t0) * NDH;
    const float* kb = k + (size_t)bh * NT * NDH;
    const float* vb = v + (size_t)bh * NT * NDH;
    const float* pb = p + (size_t)h * NSPOS * NDH;

    // q tile: 128 rows x 16 c4 = 2048 tasks
#pragma unroll
    for (int pp = 0; pp < 4; pp++) {
        int e = tid + (pp << 9);
        int r = e >> 4;
        int c4 = e & 15;
        float4 t = *(const float4*)(qb + r * NDH + (c4 << 2));
        *(float4*)(sq + r * 64 + (((c4 ^ (r & 15)) << 2))) = t;
    }

    ull O2[4][2];
    float m_i[4], l_i[4];
#pragma unroll
    for (int i = 0; i < 4; i++) {
        m_i[i] = -3.0e38f;
        l_i[i] = 0.f;
        O2[i][0] = 0ull;
        O2[i][1] = 0ull;
    }

    const int pbr = ty - tx + 31;     // band base (m = 0); in [0,46]
    const int pb15 = pbr & 15;

    for (int s0 = 0; s0 < NT; s0 += 64) {
        __syncthreads();
        // K (swizzled) and V (linear): 64 rows x 16 c4 = 1024 tasks
#pragma unroll
        for (int pp = 0; pp < 2; pp++) {
            int e = tid + (pp << 9);
            int r = e >> 4;
            int c4 = e & 15;
            float4 kk = *(const float4*)(kb + (size_t)(s0 + r) * NDH + (c4 << 2));
            *(float4*)(sk_ + r * 64 + ((c4 ^ (r & 15)) << 2)) = kk;
            float4 vv = *(const float4*)(vb + (size_t)(s0 + r) * NDH + (c4 << 2));
            *(float4*)(sv_ + r * 68 + (c4 << 2)) = vv;
        }
        // p band: 191 rows x 16 c4 = 3056 tasks
        const int pbase = 896 + s0 - t0;
#pragma unroll
        for (int pp = 0; pp < 6; pp++) {
            int e = tid + (pp << 9);
            if (e < 191 * 16) {
                int r = e >> 4;
                int c4 = e & 15;
                float4 pv4 = *(const float4*)(pb + (size_t)(pbase + r) * NDH + (c4 << 2));
                *(float4*)(sp_ + r * 64 + ((c4 ^ (r & 15)) << 2)) = pv4;
            }
        }
        if (tid < 64)  suk[tid] = uk[bh * NT + s0 + tid];
        if (tid < 191) svp[tid] = vp[h * NSPOS + pbase + tid];
        __syncthreads();

        // ---- scores: LDS.128, f32x2 FMA ----
        ull S2[4][4];
#pragma unroll
        for (int i = 0; i < 4; i++)
#pragma unroll
            for (int j = 0; j < 4; j++) S2[i][j] = 0ull;

#pragma unroll 2
        for (int c4 = 0; c4 < 16; c4++) {
            ulonglong2 qv[4], kv[4], pv[10];
            const int qoff = (c4 ^ (tx & 15)) << 2;
            const int koff = (c4 ^ ty) << 2;
            const int poff = (c4 ^ pb15) << 2;
#pragma unroll
            for (int i = 0; i < 4; i++)
                qv[i] = *(const ulonglong2*)(sq + (tx + (i << 5)) * 64 + qoff);
#pragma unroll
            for (int j = 0; j < 4; j++)
                kv[j] = *(const ulonglong2*)(sk_ + (ty + (j << 4)) * 64 + koff);
#pragma unroll
            for (int m = 0; m < 10; m++)
                pv[m] = *(const ulonglong2*)(sp_ + (pbr + (m << 4)) * 64 + poff);
#pragma unroll
            for (int i = 0; i < 4; i++)
#pragma unroll
                for (int j = 0; j < 4; j++) {
                    const int m = j - 2 * i + 6;
                    ffma2(S2[i][j], qv[i].x, kv[j].x);
                    ffma2(S2[i][j], qv[i].y, kv[j].y);
                    ffma2(S2[i][j], qv[i].x, pv[m].x);
                    ffma2(S2[i][j], qv[i].y, pv[m].y);
                }
        }

        // ---- online softmax (rows owned by 16-lane half-warps) ----
#pragma unroll
        for (int i = 0; i < 4; i++) {
            float s[4];
            float mt = -3.0e38f;
#pragma unroll
            for (int j = 0; j < 4; j++) {
                float2 f = unpk(S2[i][j]);
                s[j] = (f.x + f.y + suk[ty + (j << 4)]
                        + svp[pbr + ((j - 2 * i + 6) << 4)]) * ATT_SCALE;
                mt = fmaxf(mt, s[j]);
            }
#pragma unroll
            for (int off = 8; off >= 1; off >>= 1)
                mt = fmaxf(mt, __shfl_xor_sync(0xffffffffu, mt, off));
            float mn = fmaxf(m_i[i], mt);
            float alpha = __expf(m_i[i] - mn);
            m_i[i] = mn;
            float rs = 0.f;
#pragma unroll
            for (int j = 0; j < 4; j++) {
                float ev = __expf(s[j] - mn);
                s[j] = ev;
                rs += ev;
            }
#pragma unroll
            for (int off = 8; off >= 1; off >>= 1)
                rs += __shfl_xor_sync(0xffffffffu, rs, off);
            l_i[i] = l_i[i] * alpha + rs;
            ull ad = fdup(alpha);
            fmul2(O2[i][0], ad);
            fmul2(O2[i][1], ad);
#pragma unroll
            for (int j = 0; j < 4; j++)
                sPs[(tx + (i << 5)) * 66 + ty + (j << 4)] = s[j];
        }
        __syncthreads();

        // ---- O += P @ V ----
#pragma unroll 4
        for (int c = 0; c < 64; c++) {
            ulonglong2 vv = *(const ulonglong2*)(sv_ + c * 68 + (ty << 2));
#pragma unroll
            for (int i = 0; i < 4; i++) {
                ull pd = fdup(sPs[(tx + (i << 5)) * 66 + c]);
                ffma2(O2[i][0], pd, vv.x);
                ffma2(O2[i][1], pd, vv.y);
            }
        }
    }

    // normalize, write to [b][t][h*64+d]
#pragma unroll
    for (int i = 0; i < 4; i++) {
        float inv = 1.f / l_i[i];
        float2 a = unpk(O2[i][0]);
        float2 c2 = unpk(O2[i][1]);
        float4 o;
        o.x = a.x * inv;  o.y = a.y * inv;
        o.z = c2.x * inv; o.w = c2.y * inv;
        int r = tx + (i << 5);
        *(float4*)(out + ((size_t)b * NT + t0 + r) * ND + h * NDH + (ty << 2)) = o;
    }
}

// ---------------------------------------------------------------------------
extern "C" void kernel_launch(void* const* d_in, const int* in_sizes, int n_in,
                              void* d_out, int out_size)
{
    const float* x    = (const float*)d_in[0];
    const float* pe   = (const float*)d_in[1];
    const float* Wq   = (const float*)d_in[2];
    const float* bq   = (const float*)d_in[3];
    const float* Wk   = (const float*)d_in[4];
    const float* bk   = (const float*)d_in[5];
    const float* Wv   = (const float*)d_in[6];
    const float* bv   = (const float*)d_in[7];
    const float* Wpos = (const float*)d_in[8];
    const float* pbu  = (const float*)d_in[9];
    const float* pbv  = (const float*)d_in[10];
    const float* Wo   = (const float*)d_in[11];
    const float* bo   = (const float*)d_in[12];
    float* out = (float*)d_out;

    float *qp, *kp, *vp_, *pp, *aop, *ukp, *vpp;
    cudaGetSymbolAddress((void**)&qp,  g_q);
    cudaGetSymbolAddress((void**)&kp,  g_k);
    cudaGetSymbolAddress((void**)&vp_, g_v);
    cudaGetSymbolAddress((void**)&pp,  g_p);
    cudaGetSymbolAddress((void**)&aop, g_ao);
    cudaGetSymbolAddress((void**)&ukp, g_uk);
    cudaGetSymbolAddress((void**)&vpp, g_vp);
    __nv_bfloat16 *xh, *xl, *peh, *pel, *wth, *wtl, *aoh, *aol;
    cudaGetSymbolAddress((void**)&xh,  g_xh);
    cudaGetSymbolAddress((void**)&xl,  g_xl);
    cudaGetSymbolAddress((void**)&peh, g_peh);
    cudaGetSymbolAddress((void**)&pel, g_pel);
    cudaGetSymbolAddress((void**)&wth, g_wth);
    cudaGetSymbolAddress((void**)&wtl, g_wtl);
    cudaGetSymbolAddress((void**)&aoh, g_aoh);
    cudaGetSymbolAddress((void**)&aol, g_aol);

    cudaFuncSetAttribute(mmagemm_fused_k, cudaFuncAttributeMaxDynamicSharedMemorySize, MT_SMEM);
    cudaFuncSetAttribute(mmagemm_k<0>,    cudaFuncAttributeMaxDynamicSharedMemorySize, MT_SMEM);
    const int smem = SM_FLOATS * (int)sizeof(float);   // 150400 B
    cudaFuncSetAttribute(attn_k, cudaFuncAttributeMaxDynamicSharedMemorySize, smem);

    const size_t WSZ = (size_t)ND * ND;
    dim3 blk(256);

    split_k<<<(NB*NT*ND/4 + 255)/256, blk>>>(x,  xh,  xl,  NB*NT*ND/4);
    split_k<<<(NSPOS*ND/4 + 255)/256, blk>>>(pe, peh, pel, NSPOS*ND/4);
    wsplit_k<<<dim3(16, 16, 5), blk>>>(Wq, Wk, Wv, Wpos, Wo, wth, wtl);

    mmagemm_fused_k<<<dim3(64, 4, 4), blk, MT_SMEM>>>(xh, xl, peh, pel, wth, wtl,
                                                      bq, bk, bv, qp, kp, vp_, pp);
    biasdot_k<<<(NUKROWS + NVPROWS + 7) / 8, blk>>>(kp, pp, pbu, pbv, ukp, vpp);
    attn_k<<<NB * NH * (NT / 128), 512, smem>>>(qp, kp, vp_, pp, ukp, vpp, aop);
    split_k<<<(NB*NT*ND/4 + 255)/256, blk>>>(aop, aoh, aol, NB*NT*ND/4);
    mmagemm_k<0><<<dim3(64, 4), blk, MT_SMEM>>>(aoh, aol, wth + 4*WSZ, wtl + 4*WSZ,
                                                bo, out, NB * NT);
}